// round 1
// baseline (speedup 1.0000x reference)
#include <cuda_runtime.h>
#include <math.h>
#include <stdint.h>

// Problem constants (fixed shapes)
#define SAMPLE_RATE 24000
#define HOP 256
#define NFFT 2048
#define M_HALF 1024            // complex FFT size (real-packing)
#define NBINS 1025             // rfft bins
#define WINSZ 32
#define NPITCH 256
#define BATCH 16
#define NSAMP 480000
#define TFRAMES 1876           // 1 + 480000/256

struct Params {
    int   closest[NPITCH];
    int   shift[8];   // shift[0]=0 (n=1), shift[n-1] for harmonic n
    float wgt[8];     // wgt[0]=1
};

__global__ __launch_bounds__(256)
void pitch_kernel(const float* __restrict__ wav, float* __restrict__ out, Params p)
{
    __shared__ float2 Z[M_HALF];     // packed complex data
    __shared__ float2 TW[512];       // twiddles exp(-2*pi*i*j/1024)
    __shared__ float  LA[NBINS];     // log magnitude
    __shared__ float  LS[NPITCH];    // gathered fine structure
    __shared__ float  RED[8];

    const int tid = threadIdx.x;
    const int t   = blockIdx.x;      // frame
    const int b   = blockIdx.y;      // batch
    const float* w = wav + (size_t)b * NSAMP;

    // ---- twiddle table: TW[j] = exp(-i * pi * j / 512) ----
    for (int j = tid; j < 512; j += 256) {
        float ang = -(float)M_PI * (float)j * (1.0f / 512.0f);
        float sn, cs;
        sincosf(ang, &sn, &cs);
        TW[j] = make_float2(cs, sn);
    }

    // ---- load 2048 windowed samples (reflect pad) into bit-reversed packed slots ----
    const int base = t * HOP - (NFFT / 2);
    for (int j = tid; j < NFFT; j += 256) {
        int pos = base + j;
        if (pos < 0) pos = -pos;
        else if (pos >= NSAMP) pos = 2 * NSAMP - 2 - pos;
        float win = 0.5f - 0.5f * cosf((float)(2.0 * M_PI / (double)NFFT) * (float)j);
        float v = w[pos] * win;
        int k  = j >> 1;
        int br = __brev((unsigned)k) >> 22;   // 10-bit reversal
        if (j & 1) Z[br].y = v; else Z[br].x = v;
    }
    __syncthreads();

    // ---- 1024-pt complex FFT, radix-2 DIT, natural-order output ----
    #pragma unroll
    for (int s = 1; s <= 10; ++s) {
        const int half = 1 << (s - 1);
        #pragma unroll
        for (int rep = 0; rep < 2; ++rep) {
            int i = tid + rep * 256;         // butterfly index 0..511
            int pos = i & (half - 1);
            int grp = i >> (s - 1);
            int i1 = (grp << s) + pos;
            int i2 = i1 + half;
            float2 wt = TW[pos << (10 - s)];
            float2 a  = Z[i1];
            float2 bb = Z[i2];
            float tr = wt.x * bb.x - wt.y * bb.y;
            float ti = wt.x * bb.y + wt.y * bb.x;
            Z[i2] = make_float2(a.x - tr, a.y - ti);
            Z[i1] = make_float2(a.x + tr, a.y + ti);
        }
        __syncthreads();
    }

    // ---- unpack real FFT, magnitude, log ----
    for (int k = tid; k < NBINS; k += 256) {
        float2 A  = Z[k & (M_HALF - 1)];
        float2 Bv = Z[(M_HALF - k) & (M_HALF - 1)];
        float zer =  0.5f * (A.x + Bv.x);
        float zei =  0.5f * (A.y - Bv.y);
        float zor =  0.5f * (A.y + Bv.y);
        float zoi = -0.5f * (A.x - Bv.x);
        float ang = -(float)M_PI * (float)k * (1.0f / 1024.0f);
        float sn, cs;
        sincosf(ang, &sn, &cs);
        float xr = zer + cs * zor - sn * zoi;
        float xi = zei + cs * zoi + sn * zor;
        float mag = sqrtf(xr * xr + xi * xi);
        LA[k] = logf(mag + 1e-8f);
    }
    __syncthreads();

    // ---- fine structure at the 256 gathered bins ----
    {
        int ci = p.closest[tid];
        float sum = 0.f;
        #pragma unroll
        for (int d = -15; d <= 16; ++d) {
            int idx = ci + d;
            idx = idx < 0 ? 0 : (idx > NBINS - 1 ? NBINS - 1 : idx);
            sum += LA[idx];
        }
        float env = sum * (1.0f / (float)WINSZ);
        LS[tid] = expf(LA[ci] - env);
    }
    __syncthreads();

    // ---- subharmonic summation (sequential adds match reference order) ----
    float v = LS[tid];
    #pragma unroll
    for (int n = 1; n < 8; ++n) {
        int sh = p.shift[n];
        if (sh < NPITCH && tid >= sh) v += p.wgt[n] * LS[tid - sh];
    }

    // ---- per-frame max, normalize ----
    float m = v;
    #pragma unroll
    for (int o = 16; o; o >>= 1)
        m = fmaxf(m, __shfl_xor_sync(0xffffffffu, m, o));
    if ((tid & 31) == 0) RED[tid >> 5] = m;
    __syncthreads();
    if (tid < 32) {
        float mm = (tid < 8) ? RED[tid] : -3.4e38f;
        #pragma unroll
        for (int o = 4; o; o >>= 1)
            mm = fmaxf(mm, __shfl_xor_sync(0xffffffffu, mm, o));
        if (tid == 0) RED[0] = mm;
    }
    __syncthreads();
    float mx = fmaxf(RED[0], 1e-8f);

    out[((size_t)b * TFRAMES + t) * NPITCH + tid] = v / mx;
}

extern "C" void kernel_launch(void* const* d_in, const int* in_sizes, int n_in,
                              void* d_out, int out_size)
{
    (void)in_sizes; (void)n_in; (void)out_size;
    const float* wav = (const float*)d_in[0];
    float* out = (float*)d_out;

    Params p;

    // Gather indices: argmin over f32 |linspace(0,12000,1025) - center|,
    // center = exp(linspace(log 40, log 1000, 256)). linear step 11.71875
    // is binary exact, i*step exact in f32 (1500*i < 2^24).
    const double l40 = log(40.0), l1000 = log(1000.0);
    for (int j = 0; j < NPITCH; ++j) {
        double cd = exp(l40 + (double)j * (l1000 - l40) / 255.0);
        float  cf = (float)cd;
        const float step = 11.71875f;
        int i0 = (int)(cd / 11.71875);
        int best = 0; float bestd = 3.4e38f;
        for (int i = i0 - 2; i <= i0 + 2; ++i) {
            int ic = i < 0 ? 0 : (i > 1024 ? 1024 : i);
            float d = fabsf((float)ic * step - cf);
            if (d < bestd) { bestd = d; best = ic; }   // strict < => first-min tie (argmin)
        }
        p.closest[j] = best;
    }

    // Harmonic shifts: int(round(x)) with Python banker's rounding == rint().
    // Same libm log2 as the reference's CPython on this host.
    const double cpb = 1200.0 * log2(25.0) / 255.0;  // F_MAX/F_MIN = 25 exactly
    p.shift[0] = 0; p.wgt[0] = 1.0f;
    for (int n = 2; n <= 8; ++n) {
        int sh = (int)rint(1200.0 * log2((double)n) / cpb);
        p.shift[n - 1] = sh;
        p.wgt[n - 1]   = (float)pow(0.86, (double)(n - 1));
    }

    dim3 grid(TFRAMES, BATCH);
    pitch_kernel<<<grid, 256>>>(wav, out, p);
}

// round 2
// speedup vs baseline: 1.5612x; 1.5612x over previous
#include <cuda_runtime.h>
#include <math.h>
#include <stdint.h>

// Fixed problem shapes
#define HOP 256
#define NFFT 2048
#define MH 1024            // complex FFT size (real-packing)
#define NBINS 1025
#define WINSZ 32
#define NPITCH 256
#define BATCH 16
#define NSAMP 480000
#define TFRAMES 1876

struct Params {
    int   closest[NPITCH];
    int   shift[8];
    float wgt[8];
};

// Padded shared layout: phys(i) = i + i/4 (conflict-free at the small-L stages)
__device__ __forceinline__ int PHYS(int i) { return i + (i >> 2); }

// base-4 digit reversal of a 10-bit index: bit-reverse then swap adjacent bit pairs
__device__ __forceinline__ int DR10(int k) {
    unsigned y = __brev((unsigned)k) >> 22;
    return (int)(((y & 0x2AAu) >> 1) | ((y & 0x155u) << 1));
}

__global__ __launch_bounds__(256)
void pitch_kernel(const float* __restrict__ wav, float* __restrict__ out, Params p)
{
    __shared__ float2 Z[1280];       // 1024 complex + /4 padding
    __shared__ float  LA[NBINS];
    __shared__ float  LS[NPITCH];
    __shared__ float  RED[8];

    const int tid = threadIdx.x;
    const int t   = blockIdx.x;
    const int b   = blockIdx.y;
    const float* w = wav + (size_t)b * NSAMP;
    const int base = t * HOP - (NFFT / 2);

    // ---- load 8 windowed samples -> 4 packed complex, reflect pad on edges ----
    float fr[4], fi[4];
    const float W2PI = 6.283185307179586f / (float)NFFT;
    if (base >= 0 && base + NFFT <= NSAMP) {
        #pragma unroll
        for (int s = 0; s < 4; ++s) {
            int j = 2 * (tid + 256 * s);
            float2 xv = *reinterpret_cast<const float2*>(w + base + j);
            fr[s] = xv.x * (0.5f - 0.5f * __cosf(W2PI * (float)j));
            fi[s] = xv.y * (0.5f - 0.5f * __cosf(W2PI * (float)(j + 1)));
        }
    } else {
        #pragma unroll
        for (int s = 0; s < 4; ++s) {
            int j = 2 * (tid + 256 * s);
            int p0 = base + j, p1 = p0 + 1;
            p0 = p0 < 0 ? -p0 : (p0 >= NSAMP ? 2 * NSAMP - 2 - p0 : p0);
            p1 = p1 < 0 ? -p1 : (p1 >= NSAMP ? 2 * NSAMP - 2 - p1 : p1);
            fr[s] = w[p0] * (0.5f - 0.5f * __cosf(W2PI * (float)j));
            fi[s] = w[p1] * (0.5f - 0.5f * __cosf(W2PI * (float)(j + 1)));
        }
    }

    // ---- stage 1 (L=1024) entirely in registers: a_s = z[tid + 256 s] ----
    {
        float t0r = fr[0] + fr[2], t0i = fi[0] + fi[2];
        float t1r = fr[1] + fr[3], t1i = fi[1] + fi[3];
        float t2r = fr[0] - fr[2], t2i = fi[0] - fi[2];
        float t3r = fr[1] - fr[3], t3i = fi[1] - fi[3];
        float y0r = t0r + t1r, y0i = t0i + t1i;
        float y2r = t0r - t1r, y2i = t0i - t1i;
        float y1r = t2r + t3i, y1i = t2i - t3r;   // (a0-a2) - i(a1-a3)
        float y3r = t2r - t3i, y3i = t2i + t3r;   // (a0-a2) + i(a1-a3)
        float ang = (float)tid * (-6.283185307179586f / 1024.0f);
        float s1, c1; __sincosf(ang, &s1, &c1);
        float c2 = c1 * c1 - s1 * s1, s2 = 2.0f * c1 * s1;
        float c3 = c1 * c2 - s1 * s2, s3 = c1 * s2 + s1 * c2;
        Z[PHYS(tid)]       = make_float2(y0r, y0i);
        Z[PHYS(tid + 256)] = make_float2(y1r * c1 - y1i * s1, y1r * s1 + y1i * c1);
        Z[PHYS(tid + 512)] = make_float2(y2r * c2 - y2i * s2, y2r * s2 + y2i * c2);
        Z[PHYS(tid + 768)] = make_float2(y3r * c3 - y3i * s3, y3r * s3 + y3i * c3);
    }

    // ---- stages 2..5: L = 256, 64, 16, 4 (in-place, thread owns its 4 slots) ----
    #pragma unroll
    for (int st = 0; st < 4; ++st) {
        const int LOG2L = 8 - 2 * st;
        const int L = 1 << LOG2L;
        const int Q = L >> 2;
        __syncthreads();
        const int q  = tid & (Q - 1);
        const int i0 = ((tid >> (LOG2L - 2)) << LOG2L) + q;
        float2 a0 = Z[PHYS(i0)];
        float2 a1 = Z[PHYS(i0 + Q)];
        float2 a2 = Z[PHYS(i0 + 2 * Q)];
        float2 a3 = Z[PHYS(i0 + 3 * Q)];
        float t0r = a0.x + a2.x, t0i = a0.y + a2.y;
        float t1r = a1.x + a3.x, t1i = a1.y + a3.y;
        float t2r = a0.x - a2.x, t2i = a0.y - a2.y;
        float t3r = a1.x - a3.x, t3i = a1.y - a3.y;
        float y0r = t0r + t1r, y0i = t0i + t1i;
        float y2r = t0r - t1r, y2i = t0i - t1i;
        float y1r = t2r + t3i, y1i = t2i - t3r;
        float y3r = t2r - t3i, y3i = t2i + t3r;
        if (Q > 1) {
            float ang = (float)q * (-6.283185307179586f / (float)L);
            float s1, c1; __sincosf(ang, &s1, &c1);
            float c2 = c1 * c1 - s1 * s1, s2 = 2.0f * c1 * s1;
            float c3 = c1 * c2 - s1 * s2, s3 = c1 * s2 + s1 * c2;
            Z[PHYS(i0)]         = make_float2(y0r, y0i);
            Z[PHYS(i0 + Q)]     = make_float2(y1r * c1 - y1i * s1, y1r * s1 + y1i * c1);
            Z[PHYS(i0 + 2 * Q)] = make_float2(y2r * c2 - y2i * s2, y2r * s2 + y2i * c2);
            Z[PHYS(i0 + 3 * Q)] = make_float2(y3r * c3 - y3i * s3, y3r * s3 + y3i * c3);
        } else {
            Z[PHYS(i0)]     = make_float2(y0r, y0i);
            Z[PHYS(i0 + 1)] = make_float2(y1r, y1i);
            Z[PHYS(i0 + 2)] = make_float2(y2r, y2i);
            Z[PHYS(i0 + 3)] = make_float2(y3r, y3i);
        }
    }
    __syncthreads();

    // ---- unpack real FFT (data is digit-reversed), magnitude, log ----
    for (int k = tid; k < NBINS; k += 256) {
        float2 A  = Z[PHYS(DR10(k & (MH - 1)))];
        float2 Bv = Z[PHYS(DR10((MH - k) & (MH - 1)))];
        float zer =  0.5f * (A.x + Bv.x);
        float zei =  0.5f * (A.y - Bv.y);
        float zor =  0.5f * (A.y + Bv.y);
        float zoi = -0.5f * (A.x - Bv.x);
        float sn, cs;
        __sincosf((float)k * (-3.141592653589793f / 1024.0f), &sn, &cs);
        float xr = zer + cs * zor - sn * zoi;
        float xi = zei + cs * zoi + sn * zor;
        LA[k] = __logf(sqrtf(xr * xr + xi * xi) + 1e-8f);
    }
    __syncthreads();

    // ---- fine structure at the 256 gathered bins ----
    {
        int ci = p.closest[tid];
        float sum = 0.f;
        #pragma unroll
        for (int d = -15; d <= 16; ++d) {
            int idx = ci + d;
            idx = idx < 0 ? 0 : (idx > NBINS - 1 ? NBINS - 1 : idx);
            sum += LA[idx];
        }
        float env = sum * (1.0f / (float)WINSZ);
        LS[tid] = __expf(LA[ci] - env);
    }
    __syncthreads();

    // ---- subharmonic summation ----
    float v = LS[tid];
    #pragma unroll
    for (int n = 1; n < 8; ++n) {
        int sh = p.shift[n];
        if (sh < NPITCH && tid >= sh) v += p.wgt[n] * LS[tid - sh];
    }

    // ---- per-frame max, normalize ----
    float m = v;
    #pragma unroll
    for (int o = 16; o; o >>= 1)
        m = fmaxf(m, __shfl_xor_sync(0xffffffffu, m, o));
    if ((tid & 31) == 0) RED[tid >> 5] = m;
    __syncthreads();
    if (tid < 32) {
        float mm = (tid < 8) ? RED[tid] : -3.4e38f;
        #pragma unroll
        for (int o = 4; o; o >>= 1)
            mm = fmaxf(mm, __shfl_xor_sync(0xffffffffu, mm, o));
        if (tid == 0) RED[0] = mm;
    }
    __syncthreads();
    float mx = fmaxf(RED[0], 1e-8f);

    out[((size_t)b * TFRAMES + t) * NPITCH + tid] = v / mx;
}

extern "C" void kernel_launch(void* const* d_in, const int* in_sizes, int n_in,
                              void* d_out, int out_size)
{
    (void)in_sizes; (void)n_in; (void)out_size;
    const float* wav = (const float*)d_in[0];
    float* out = (float*)d_out;

    Params p;

    // Gather indices: f32 argmin over |linspace(0,12000,1025) - center_freq|
    const double l40 = log(40.0), l1000 = log(1000.0);
    for (int j = 0; j < NPITCH; ++j) {
        double cd = exp(l40 + (double)j * (l1000 - l40) / 255.0);
        float  cf = (float)cd;
        const float step = 11.71875f;
        int i0 = (int)(cd / 11.71875);
        int best = 0; float bestd = 3.4e38f;
        for (int i = i0 - 2; i <= i0 + 2; ++i) {
            int ic = i < 0 ? 0 : (i > 1024 ? 1024 : i);
            float d = fabsf((float)ic * step - cf);
            if (d < bestd) { bestd = d; best = ic; }
        }
        p.closest[j] = best;
    }

    // Harmonic shifts: Python round() == rint (half-even)
    const double cpb = 1200.0 * log2(25.0) / 255.0;
    p.shift[0] = 0; p.wgt[0] = 1.0f;
    for (int n = 2; n <= 8; ++n) {
        p.shift[n - 1] = (int)rint(1200.0 * log2((double)n) / cpb);
        p.wgt[n - 1]   = (float)pow(0.86, (double)(n - 1));
    }

    dim3 grid(TFRAMES, BATCH);
    pitch_kernel<<<grid, 256>>>(wav, out, p);
}

// round 3
// speedup vs baseline: 3.0247x; 1.9374x over previous
#include <cuda_runtime.h>
#include <math.h>
#include <stdint.h>

// Fixed problem shapes
#define HOP 256
#define NFFT 2048
#define MH 1024            // complex FFT size (real-packing)
#define WINSZ 32
#define NPITCH 256
#define BATCH 16
#define NSAMP 480000
#define TFRAMES 1876
#define KMAX 102           // only rfft bins 0..101 are ever consumed

struct Params {
    int   closest[NPITCH];
    int   shift[8];
    float wgt[8];
};

// Padded shared layout: phys(i) = i + i/4
__device__ __forceinline__ int PHYS(int i) { return i + (i >> 2); }

__global__ __launch_bounds__(256)
void pitch_kernel(const float* __restrict__ wav, float* __restrict__ out, Params p)
{
    __shared__ float2 Z[1280];        // 1024 complex + padding
    __shared__ float2 SPA[KMAX];      // FFT bins 0..101 (natural order)
    __shared__ float2 SPB[101];       // FFT bins 923..1023 (SPB[m] = bin 923+m)
    __shared__ float  LA[KMAX];       // log magnitude, bins 0..101
    __shared__ float  CS[KMAX + 1];   // prefix sums of LA
    __shared__ float  LS[NPITCH];
    __shared__ float  RED[8];

    const int tid = threadIdx.x;
    const int t   = blockIdx.x;
    const int b   = blockIdx.y;
    const float* w = wav + (size_t)b * NSAMP;
    const int base = t * HOP - (NFFT / 2);

    // ---- load 8 windowed samples -> 4 packed complex, reflect pad on edges ----
    float fr[4], fi[4];
    const float W2PI = 6.283185307179586f / (float)NFFT;
    if (base >= 0 && base + NFFT <= NSAMP) {
        #pragma unroll
        for (int s = 0; s < 4; ++s) {
            int j = 2 * (tid + 256 * s);
            float2 xv = *reinterpret_cast<const float2*>(w + base + j);
            fr[s] = xv.x * (0.5f - 0.5f * __cosf(W2PI * (float)j));
            fi[s] = xv.y * (0.5f - 0.5f * __cosf(W2PI * (float)(j + 1)));
        }
    } else {
        #pragma unroll
        for (int s = 0; s < 4; ++s) {
            int j = 2 * (tid + 256 * s);
            int p0 = base + j, p1 = p0 + 1;
            p0 = p0 < 0 ? -p0 : (p0 >= NSAMP ? 2 * NSAMP - 2 - p0 : p0);
            p1 = p1 < 0 ? -p1 : (p1 >= NSAMP ? 2 * NSAMP - 2 - p1 : p1);
            fr[s] = w[p0] * (0.5f - 0.5f * __cosf(W2PI * (float)j));
            fi[s] = w[p1] * (0.5f - 0.5f * __cosf(W2PI * (float)(j + 1)));
        }
    }

    // ---- stage 1 (L=1024) in registers ----
    {
        float t0r = fr[0] + fr[2], t0i = fi[0] + fi[2];
        float t1r = fr[1] + fr[3], t1i = fi[1] + fi[3];
        float t2r = fr[0] - fr[2], t2i = fi[0] - fi[2];
        float t3r = fr[1] - fr[3], t3i = fi[1] - fi[3];
        float y0r = t0r + t1r, y0i = t0i + t1i;
        float y2r = t0r - t1r, y2i = t0i - t1i;
        float y1r = t2r + t3i, y1i = t2i - t3r;
        float y3r = t2r - t3i, y3i = t2i + t3r;
        float ang = (float)tid * (-6.283185307179586f / 1024.0f);
        float s1, c1; __sincosf(ang, &s1, &c1);
        float c2 = c1 * c1 - s1 * s1, s2 = 2.0f * c1 * s1;
        float c3 = c1 * c2 - s1 * s2, s3 = c1 * s2 + s1 * c2;
        Z[PHYS(tid)]       = make_float2(y0r, y0i);
        Z[PHYS(tid + 256)] = make_float2(y1r * c1 - y1i * s1, y1r * s1 + y1i * c1);
        Z[PHYS(tid + 512)] = make_float2(y2r * c2 - y2i * s2, y2r * s2 + y2i * c2);
        Z[PHYS(tid + 768)] = make_float2(y3r * c3 - y3i * s3, y3r * s3 + y3i * c3);
    }

    // ---- stages 2..4: L = 256, 64, 16 ----
    #pragma unroll
    for (int st = 0; st < 3; ++st) {
        const int LOG2L = 8 - 2 * st;
        const int L = 1 << LOG2L;
        const int Q = L >> 2;
        __syncthreads();
        const int q  = tid & (Q - 1);
        const int i0 = ((tid >> (LOG2L - 2)) << LOG2L) + q;
        float2 a0 = Z[PHYS(i0)];
        float2 a1 = Z[PHYS(i0 + Q)];
        float2 a2 = Z[PHYS(i0 + 2 * Q)];
        float2 a3 = Z[PHYS(i0 + 3 * Q)];
        float t0r = a0.x + a2.x, t0i = a0.y + a2.y;
        float t1r = a1.x + a3.x, t1i = a1.y + a3.y;
        float t2r = a0.x - a2.x, t2i = a0.y - a2.y;
        float t3r = a1.x - a3.x, t3i = a1.y - a3.y;
        float y0r = t0r + t1r, y0i = t0i + t1i;
        float y2r = t0r - t1r, y2i = t0i - t1i;
        float y1r = t2r + t3i, y1i = t2i - t3r;
        float y3r = t2r - t3i, y3i = t2i + t3r;
        float ang = (float)q * (-6.283185307179586f / (float)L);
        float s1, c1; __sincosf(ang, &s1, &c1);
        float c2 = c1 * c1 - s1 * s1, s2 = 2.0f * c1 * s1;
        float c3 = c1 * c2 - s1 * s2, s3 = c1 * s2 + s1 * c2;
        Z[PHYS(i0)]         = make_float2(y0r, y0i);
        Z[PHYS(i0 + Q)]     = make_float2(y1r * c1 - y1i * s1, y1r * s1 + y1i * c1);
        Z[PHYS(i0 + 2 * Q)] = make_float2(y2r * c2 - y2i * s2, y2r * s2 + y2i * c2);
        Z[PHYS(i0 + 3 * Q)] = make_float2(y3r * c3 - y3i * s3, y3r * s3 + y3i * c3);
    }
    __syncthreads();

    // ---- stage 5 (L=4): butterfly g=tid produces bins {r, r+256, r+512, r+768},
    //      r = base4-digit-reverse(tid). Only bins r (<=101) and r+768 (>=923) are
    //      needed; store them bin-indexed so unpack reads are linear. ----
    {
        const int i0 = tid << 2;
        float2 a0 = Z[PHYS(i0)];
        float2 a1 = Z[PHYS(i0 + 1)];
        float2 a2 = Z[PHYS(i0 + 2)];
        float2 a3 = Z[PHYS(i0 + 3)];
        float t0r = a0.x + a2.x, t0i = a0.y + a2.y;
        float t1r = a1.x + a3.x, t1i = a1.y + a3.y;
        float t2r = a0.x - a2.x, t2i = a0.y - a2.y;
        float t3r = a1.x - a3.x, t3i = a1.y - a3.y;
        unsigned y = __brev((unsigned)tid) >> 24;
        int r = (int)(((y & 0xAAu) >> 1) | ((y & 0x55u) << 1));
        if (r < KMAX)  SPA[r]       = make_float2(t0r + t1r, t0i + t1i);         // bin r
        if (r >= 155)  SPB[r - 155] = make_float2(t2r - t3i, t2i + t3r);         // bin r+768
    }
    __syncthreads();

    // ---- unpack real FFT + magnitude + log, bins 0..101 only ----
    if (tid < KMAX) {
        float2 A  = SPA[tid];
        float2 Bv = (tid == 0) ? SPA[0] : SPB[101 - tid];   // bin (1024 - k)
        float zer =  0.5f * (A.x + Bv.x);
        float zei =  0.5f * (A.y - Bv.y);
        float zor =  0.5f * (A.y + Bv.y);
        float zoi = -0.5f * (A.x - Bv.x);
        float sn, cs;
        __sincosf((float)tid * (-3.141592653589793f / 1024.0f), &sn, &cs);
        float xr = zer + cs * zor - sn * zoi;
        float xi = zei + cs * zoi + sn * zor;
        LA[tid] = __logf(sqrtf(xr * xr + xi * xi) + 1e-8f);
    }
    __syncthreads();

    // ---- prefix sum of LA[0..101] by warp 0 ----
    if (tid < 32) {
        float carry = 0.f;
        #pragma unroll
        for (int c = 0; c < 4; ++c) {
            int idx = c * 32 + tid;
            float v = (idx < KMAX) ? LA[idx] : 0.f;
            #pragma unroll
            for (int o = 1; o < 32; o <<= 1) {
                float u = __shfl_up_sync(0xffffffffu, v, o);
                if (tid >= o) v += u;
            }
            float tot = __shfl_sync(0xffffffffu, v, 31);
            v += carry;
            if (idx < KMAX) CS[idx + 1] = v;
            carry += tot;
        }
        if (tid == 0) CS[0] = 0.f;
    }
    __syncthreads();

    // ---- fine structure at the 256 gathered bins (window sum via cumsum) ----
    {
        int ci = p.closest[tid];          // 3..85, so hi <= 101 always
        int lo = ci - 15, hi = ci + 16;
        float sum = (lo < 0) ? ((float)(-lo) * LA[0] + CS[hi + 1])
                             : (CS[hi + 1] - CS[lo]);
        LS[tid] = __expf(LA[ci] - sum * (1.0f / (float)WINSZ));
    }
    __syncthreads();

    // ---- subharmonic summation ----
    float v = LS[tid];
    #pragma unroll
    for (int n = 1; n < 8; ++n) {
        int sh = p.shift[n];
        if (sh < NPITCH && tid >= sh) v += p.wgt[n] * LS[tid - sh];
    }

    // ---- per-frame max, normalize ----
    float m = v;
    #pragma unroll
    for (int o = 16; o; o >>= 1)
        m = fmaxf(m, __shfl_xor_sync(0xffffffffu, m, o));
    if ((tid & 31) == 0) RED[tid >> 5] = m;
    __syncthreads();
    if (tid < 32) {
        float mm = (tid < 8) ? RED[tid] : -3.4e38f;
        #pragma unroll
        for (int o = 4; o; o >>= 1)
            mm = fmaxf(mm, __shfl_xor_sync(0xffffffffu, mm, o));
        if (tid == 0) RED[0] = mm;
    }
    __syncthreads();
    float mx = fmaxf(RED[0], 1e-8f);

    out[((size_t)b * TFRAMES + t) * NPITCH + tid] = v / mx;
}

extern "C" void kernel_launch(void* const* d_in, const int* in_sizes, int n_in,
                              void* d_out, int out_size)
{
    (void)in_sizes; (void)n_in; (void)out_size;
    const float* wav = (const float*)d_in[0];
    float* out = (float*)d_out;

    Params p;

    // Gather indices: f32 argmin over |linspace(0,12000,1025) - center_freq|
    const double l40 = log(40.0), l1000 = log(1000.0);
    for (int j = 0; j < NPITCH; ++j) {
        double cd = exp(l40 + (double)j * (l1000 - l40) / 255.0);
        float  cf = (float)cd;
        const float step = 11.71875f;
        int i0 = (int)(cd / 11.71875);
        int best = 0; float bestd = 3.4e38f;
        for (int i = i0 - 2; i <= i0 + 2; ++i) {
            int ic = i < 0 ? 0 : (i > 1024 ? 1024 : i);
            float d = fabsf((float)ic * step - cf);
            if (d < bestd) { bestd = d; best = ic; }
        }
        p.closest[j] = best;
    }

    // Harmonic shifts: Python round() == rint (half-even)
    const double cpb = 1200.0 * log2(25.0) / 255.0;
    p.shift[0] = 0; p.wgt[0] = 1.0f;
    for (int n = 2; n <= 8; ++n) {
        p.shift[n - 1] = (int)rint(1200.0 * log2((double)n) / cpb);
        p.wgt[n - 1]   = (float)pow(0.86, (double)(n - 1));
    }

    dim3 grid(TFRAMES, BATCH);
    pitch_kernel<<<grid, 256>>>(wav, out, p);
}

// round 4
// speedup vs baseline: 3.1480x; 1.0408x over previous
#include <cuda_runtime.h>
#include <math.h>
#include <stdint.h>

// Fixed problem shapes
#define HOP 256
#define NFFT 2048
#define MH 1024
#define WINSZ 32
#define NPITCH 256
#define BATCH 16
#define NSAMP 480000
#define TFRAMES 1876
#define KMAX 102           // only rfft bins 0..101 are ever consumed

struct Params {
    int   closest[NPITCH];
    int   shift[8];
    float wgt[8];
};

// ---- precomputed constant tables (filled by init kernel each launch) ----
__device__ float  g_win[NFFT];     // hann window
__device__ float2 g_twa[256];      // stage1: W1024^q
__device__ float2 g_twb[64];       // stage2: W256^q
__device__ float2 g_twc[16];       // stage3: W64^q
__device__ float2 g_twd[4];        // stage4: W16^q
__device__ float2 g_upw[KMAX];     // unpack: exp(-i pi k / 1024)

__global__ void init_tables()
{
    const int tid = threadIdx.x;
    for (int j = tid; j < NFFT; j += 256)
        g_win[j] = 0.5f - 0.5f * cosf((float)(2.0 * M_PI / (double)NFFT) * (float)j);
    {
        float sn, cs;
        sincosf((float)tid * (-6.283185307179586f / 1024.0f), &sn, &cs);
        g_twa[tid] = make_float2(cs, sn);
    }
    if (tid < 64) {
        float sn, cs;
        sincosf((float)tid * (-6.283185307179586f / 256.0f), &sn, &cs);
        g_twb[tid] = make_float2(cs, sn);
    }
    if (tid < 16) {
        float sn, cs;
        sincosf((float)tid * (-6.283185307179586f / 64.0f), &sn, &cs);
        g_twc[tid] = make_float2(cs, sn);
    }
    if (tid < 4) {
        float sn, cs;
        sincosf((float)tid * (-6.283185307179586f / 16.0f), &sn, &cs);
        g_twd[tid] = make_float2(cs, sn);
    }
    if (tid < KMAX) {
        float sn, cs;
        sincosf((float)tid * (-3.141592653589793f / 1024.0f), &sn, &cs);
        g_upw[tid] = make_float2(cs, sn);
    }
}

// Padded shared layout: phys(i) = i + i/4
__device__ __forceinline__ int PHYS(int i) { return i + (i >> 2); }

__global__ __launch_bounds__(256)
void pitch_kernel(const float* __restrict__ wav, float* __restrict__ out, Params p)
{
    __shared__ float2 Z[1280];
    __shared__ float2 SPA[KMAX];      // FFT bins 0..101
    __shared__ float2 SPB[101];       // FFT bins 923..1023 (SPB[m] = bin 923+m)
    __shared__ float  LA[KMAX];
    __shared__ float  CS[KMAX + 1];
    __shared__ float  LS[NPITCH];
    __shared__ float  RED[8];

    const int tid = threadIdx.x;
    const int t   = blockIdx.x;
    const int b   = blockIdx.y;
    const float* w = wav + (size_t)b * NSAMP;
    const int base = t * HOP - (NFFT / 2);

    // ---- load 8 windowed samples -> 4 packed complex, reflect pad on edges ----
    float fr[4], fi[4];
    if (base >= 0 && base + NFFT <= NSAMP) {
        #pragma unroll
        for (int s = 0; s < 4; ++s) {
            int j = 2 * (tid + 256 * s);
            float2 xv = *reinterpret_cast<const float2*>(w + base + j);
            float2 wv = *reinterpret_cast<const float2*>(&g_win[j]);
            fr[s] = xv.x * wv.x;
            fi[s] = xv.y * wv.y;
        }
    } else {
        #pragma unroll
        for (int s = 0; s < 4; ++s) {
            int j = 2 * (tid + 256 * s);
            int p0 = base + j, p1 = p0 + 1;
            p0 = p0 < 0 ? -p0 : (p0 >= NSAMP ? 2 * NSAMP - 2 - p0 : p0);
            p1 = p1 < 0 ? -p1 : (p1 >= NSAMP ? 2 * NSAMP - 2 - p1 : p1);
            float2 wv = *reinterpret_cast<const float2*>(&g_win[j]);
            fr[s] = w[p0] * wv.x;
            fi[s] = w[p1] * wv.y;
        }
    }

    // ---- stage 1 (L=1024) in registers ----
    {
        float t0r = fr[0] + fr[2], t0i = fi[0] + fi[2];
        float t1r = fr[1] + fr[3], t1i = fi[1] + fi[3];
        float t2r = fr[0] - fr[2], t2i = fi[0] - fi[2];
        float t3r = fr[1] - fr[3], t3i = fi[1] - fi[3];
        float y0r = t0r + t1r, y0i = t0i + t1i;
        float y2r = t0r - t1r, y2i = t0i - t1i;
        float y1r = t2r + t3i, y1i = t2i - t3r;
        float y3r = t2r - t3i, y3i = t2i + t3r;
        float2 wt = g_twa[tid];
        float c1 = wt.x, s1 = wt.y;
        float c2 = c1 * c1 - s1 * s1, s2 = 2.0f * c1 * s1;
        float c3 = c1 * c2 - s1 * s2, s3 = c1 * s2 + s1 * c2;
        Z[PHYS(tid)]       = make_float2(y0r, y0i);
        Z[PHYS(tid + 256)] = make_float2(y1r * c1 - y1i * s1, y1r * s1 + y1i * c1);
        Z[PHYS(tid + 512)] = make_float2(y2r * c2 - y2i * s2, y2r * s2 + y2i * c2);
        Z[PHYS(tid + 768)] = make_float2(y3r * c3 - y3i * s3, y3r * s3 + y3i * c3);
    }

    // ---- stages 2..4: L = 256, 64, 16 ----
    #pragma unroll
    for (int st = 0; st < 3; ++st) {
        const int LOG2L = 8 - 2 * st;
        const int L = 1 << LOG2L;
        const int Q = L >> 2;
        __syncthreads();
        const int q  = tid & (Q - 1);
        const int i0 = ((tid >> (LOG2L - 2)) << LOG2L) + q;
        float2 a0 = Z[PHYS(i0)];
        float2 a1 = Z[PHYS(i0 + Q)];
        float2 a2 = Z[PHYS(i0 + 2 * Q)];
        float2 a3 = Z[PHYS(i0 + 3 * Q)];
        float t0r = a0.x + a2.x, t0i = a0.y + a2.y;
        float t1r = a1.x + a3.x, t1i = a1.y + a3.y;
        float t2r = a0.x - a2.x, t2i = a0.y - a2.y;
        float t3r = a1.x - a3.x, t3i = a1.y - a3.y;
        float y0r = t0r + t1r, y0i = t0i + t1i;
        float y2r = t0r - t1r, y2i = t0i - t1i;
        float y1r = t2r + t3i, y1i = t2i - t3r;
        float y3r = t2r - t3i, y3i = t2i + t3r;
        float2 wt = (st == 0) ? g_twb[q] : (st == 1) ? g_twc[q] : g_twd[q];
        float c1 = wt.x, s1 = wt.y;
        float c2 = c1 * c1 - s1 * s1, s2 = 2.0f * c1 * s1;
        float c3 = c1 * c2 - s1 * s2, s3 = c1 * s2 + s1 * c2;
        Z[PHYS(i0)]         = make_float2(y0r, y0i);
        Z[PHYS(i0 + Q)]     = make_float2(y1r * c1 - y1i * s1, y1r * s1 + y1i * c1);
        Z[PHYS(i0 + 2 * Q)] = make_float2(y2r * c2 - y2i * s2, y2r * s2 + y2i * c2);
        Z[PHYS(i0 + 3 * Q)] = make_float2(y3r * c3 - y3i * s3, y3r * s3 + y3i * c3);
    }
    __syncthreads();

    // ---- stage 5 (L=4), pruned: butterfly g=tid produces bins {r, r+256, r+512, r+768},
    //      r = digit-reverse(tid). Only bin r (r<102) or bin r+768 (r>=155) is consumed.
    {
        unsigned y = __brev((unsigned)tid) >> 24;
        int r = (int)(((y & 0xAAu) >> 1) | ((y & 0x55u) << 1));
        if (r < KMAX) {
            const int i0 = tid << 2;
            float2 a0 = Z[PHYS(i0)];
            float2 a1 = Z[PHYS(i0 + 1)];
            float2 a2 = Z[PHYS(i0 + 2)];
            float2 a3 = Z[PHYS(i0 + 3)];
            SPA[r] = make_float2((a0.x + a2.x) + (a1.x + a3.x),
                                 (a0.y + a2.y) + (a1.y + a3.y));
        } else if (r >= 155) {
            const int i0 = tid << 2;
            float2 a0 = Z[PHYS(i0)];
            float2 a1 = Z[PHYS(i0 + 1)];
            float2 a2 = Z[PHYS(i0 + 2)];
            float2 a3 = Z[PHYS(i0 + 3)];
            float t2r = a0.x - a2.x, t2i = a0.y - a2.y;
            float t3r = a1.x - a3.x, t3i = a1.y - a3.y;
            SPB[r - 155] = make_float2(t2r - t3i, t2i + t3r);   // bin r+768
        }
    }
    __syncthreads();

    // ---- unpack real FFT + magnitude + log, bins 0..101 only ----
    if (tid < KMAX) {
        float2 A  = SPA[tid];
        float2 Bv = (tid == 0) ? SPA[0] : SPB[101 - tid];   // bin (1024 - k)
        float zer =  0.5f * (A.x + Bv.x);
        float zei =  0.5f * (A.y - Bv.y);
        float zor =  0.5f * (A.y + Bv.y);
        float zoi = -0.5f * (A.x - Bv.x);
        float2 u = g_upw[tid];
        float cs = u.x, sn = u.y;
        float xr = zer + cs * zor - sn * zoi;
        float xi = zei + cs * zoi + sn * zor;
        LA[tid] = __logf(sqrtf(xr * xr + xi * xi) + 1e-8f);
    }
    __syncthreads();

    // ---- prefix sum of LA[0..101] by warp 0 ----
    if (tid < 32) {
        float carry = 0.f;
        #pragma unroll
        for (int c = 0; c < 4; ++c) {
            int idx = c * 32 + tid;
            float v = (idx < KMAX) ? LA[idx] : 0.f;
            #pragma unroll
            for (int o = 1; o < 32; o <<= 1) {
                float u = __shfl_up_sync(0xffffffffu, v, o);
                if (tid >= o) v += u;
            }
            float tot = __shfl_sync(0xffffffffu, v, 31);
            v += carry;
            if (idx < KMAX) CS[idx + 1] = v;
            carry += tot;
        }
        if (tid == 0) CS[0] = 0.f;
    }
    __syncthreads();

    // ---- fine structure at the 256 gathered bins ----
    {
        int ci = p.closest[tid];          // 3..85
        int lo = ci - 15, hi = ci + 16;
        float sum = (lo < 0) ? ((float)(-lo) * LA[0] + CS[hi + 1])
                             : (CS[hi + 1] - CS[lo]);
        LS[tid] = __expf(LA[ci] - sum * (1.0f / (float)WINSZ));
    }
    __syncthreads();

    // ---- subharmonic summation ----
    float v = LS[tid];
    #pragma unroll
    for (int n = 1; n < 8; ++n) {
        int sh = p.shift[n];
        if (sh < NPITCH && tid >= sh) v += p.wgt[n] * LS[tid - sh];
    }

    // ---- per-frame max, normalize ----
    float m = v;
    #pragma unroll
    for (int o = 16; o; o >>= 1)
        m = fmaxf(m, __shfl_xor_sync(0xffffffffu, m, o));
    if ((tid & 31) == 0) RED[tid >> 5] = m;
    __syncthreads();
    if (tid < 32) {
        float mm = (tid < 8) ? RED[tid] : -3.4e38f;
        #pragma unroll
        for (int o = 4; o; o >>= 1)
            mm = fmaxf(mm, __shfl_xor_sync(0xffffffffu, mm, o));
        if (tid == 0) RED[0] = mm;
    }
    __syncthreads();
    float mx = fmaxf(RED[0], 1e-8f);

    out[((size_t)b * TFRAMES + t) * NPITCH + tid] = __fdividef(v, mx);
}

extern "C" void kernel_launch(void* const* d_in, const int* in_sizes, int n_in,
                              void* d_out, int out_size)
{
    (void)in_sizes; (void)n_in; (void)out_size;
    const float* wav = (const float*)d_in[0];
    float* out = (float*)d_out;

    Params p;

    // Gather indices: f32 argmin over |linspace(0,12000,1025) - center_freq|
    const double l40 = log(40.0), l1000 = log(1000.0);
    for (int j = 0; j < NPITCH; ++j) {
        double cd = exp(l40 + (double)j * (l1000 - l40) / 255.0);
        float  cf = (float)cd;
        const float step = 11.71875f;
        int i0 = (int)(cd / 11.71875);
        int best = 0; float bestd = 3.4e38f;
        for (int i = i0 - 2; i <= i0 + 2; ++i) {
            int ic = i < 0 ? 0 : (i > 1024 ? 1024 : i);
            float d = fabsf((float)ic * step - cf);
            if (d < bestd) { bestd = d; best = ic; }
        }
        p.closest[j] = best;
    }

    // Harmonic shifts: Python round() == rint (half-even)
    const double cpb = 1200.0 * log2(25.0) / 255.0;
    p.shift[0] = 0; p.wgt[0] = 1.0f;
    for (int n = 2; n <= 8; ++n) {
        p.shift[n - 1] = (int)rint(1200.0 * log2((double)n) / cpb);
        p.wgt[n - 1]   = (float)pow(0.86, (double)(n - 1));
    }

    init_tables<<<1, 256>>>();
    dim3 grid(TFRAMES, BATCH);
    pitch_kernel<<<grid, 256>>>(wav, out, p);
}

// round 5
// speedup vs baseline: 4.8595x; 1.5437x over previous
#include <cuda_runtime.h>
#include <math.h>
#include <stdint.h>

// Fixed problem shapes
#define HOP 256
#define NFFT 2048
#define MH 1024
#define WINSZ 32
#define NPITCH 256
#define BATCH 16
#define NSAMP 480000
#define TFRAMES 1876
#define KU 103            // rfft bins 0..102 needed (102 for LA, +1 conv neighbor)
#define KLA 102           // LA/fine-structure bins 0..101

struct Params {
    int      closest[NPITCH];
    int      shift[8];
    float    wgt[8];
    unsigned live[8];     // liveness of the 256 final (d0-stage) butterflies
};

// shared padding: conflict-free for strides {1,4,16,64} access patterns used here
__device__ __forceinline__ int PHYS(int i) { return i + 4 * (i >> 6); }

// reverse the 4 base-4 digits of an 8-bit value
__device__ __forceinline__ int R4(int k) {
    unsigned y = __brev((unsigned)k) >> 24;
    return (int)(((y & 0xAAu) >> 1) | ((y & 0x55u) << 1));
}

// radix-4 DIF butterfly, twiddles applied to y1,y2,y3 (same convention as prior rounds)
__device__ __forceinline__ void bfly4(
    float& r0, float& i0, float& r1, float& i1,
    float& r2, float& i2, float& r3, float& i3,
    float c1, float s1, float c2, float s2, float c3, float s3)
{
    float t0r = r0 + r2, t0i = i0 + i2;
    float t1r = r1 + r3, t1i = i1 + i3;
    float t2r = r0 - r2, t2i = i0 - i2;
    float t3r = r1 - r3, t3i = i1 - i3;
    float y0r = t0r + t1r, y0i = t0i + t1i;
    float y2r = t0r - t1r, y2i = t0i - t1i;
    float y1r = t2r + t3i, y1i = t2i - t3r;
    float y3r = t2r - t3i, y3i = t2i + t3r;
    r0 = y0r;                         i0 = y0i;
    r1 = y1r * c1 - y1i * s1;         i1 = y1r * s1 + y1i * c1;
    r2 = y2r * c2 - y2i * s2;         i2 = y2r * s2 + y2i * c2;
    r3 = y3r * c3 - y3i * s3;         i3 = y3r * s3 + y3i * c3;
}

#define CA 0.9238795325112867f   // cos(pi/8)
#define CB 0.3826834323650898f   // sin(pi/8)
#define CR 0.7071067811865476f   // sqrt(2)/2

__global__ __launch_bounds__(64)
void pitch_kernel(const float* __restrict__ wav, float* __restrict__ out, Params p)
{
    __shared__ float2 Z[1084];       // 1024 complex with stride-64 padding
    __shared__ float2 SPA[KU];       // FFT bins 0..102
    __shared__ float2 SPB[102];      // FFT bins 922..1023 (SPB[m] = bin 922+m)
    __shared__ float2 SPX[KU];       // unpacked rfft bins 0..102 (raw, unwindowed)
    __shared__ float  LA[KLA];
    __shared__ float  CS[KLA + 1];
    __shared__ float  LS[NPITCH];
    __shared__ float  RED[2];

    const int tid = threadIdx.x;     // 0..63
    const int t   = blockIdx.x;
    const int b   = blockIdx.y;
    const float* w = wav + (size_t)b * NSAMP;
    const int base = t * HOP - (NFFT / 2);

    // ================= Phase A: load 16 packed complex + stages d4,d3 in regs ====
    float er[16], ei[16];
    if (base >= 0 && base + NFFT <= NSAMP) {
        const float2* src = reinterpret_cast<const float2*>(w + base) ;
        #pragma unroll
        for (int k = 0; k < 16; ++k) {
            float2 xv = src[tid + 64 * k];
            er[k] = xv.x; ei[k] = xv.y;
        }
    } else {
        #pragma unroll
        for (int k = 0; k < 16; ++k) {
            int n  = tid + 64 * k;
            int p0 = base + 2 * n, p1 = p0 + 1;
            p0 = p0 < 0 ? -p0 : (p0 >= NSAMP ? 2 * NSAMP - 2 - p0 : p0);
            p1 = p1 < 0 ? -p1 : (p1 >= NSAMP ? 2 * NSAMP - 2 - p1 : p1);
            er[k] = w[p0]; ei[k] = w[p1];
        }
    }

    {
        // stage d4 (L=1024): tw_j = W1024^{q j} * W16^{k0 j}
        float c1, s1; __sincosf((float)tid * (-6.283185307179586f / 1024.0f), &s1, &c1);
        float c2 = c1 * c1 - s1 * s1, s2 = 2.0f * c1 * s1;
        float c3 = c1 * c2 - s1 * s2, s3 = c1 * s2 + s1 * c2;
        // k0 = 0
        bfly4(er[0], ei[0], er[4], ei[4], er[8], ei[8], er[12], ei[12],
              c1, s1, c2, s2, c3, s3);
        // k0 = 1: K1=(CA,-CB) K2=(CR,-CR) K3=(CB,-CA)
        bfly4(er[1], ei[1], er[5], ei[5], er[9], ei[9], er[13], ei[13],
              c1 * CA + s1 * CB, s1 * CA - c1 * CB,
              (c2 + s2) * CR,    (s2 - c2) * CR,
              c3 * CB + s3 * CA, s3 * CB - c3 * CA);
        // k0 = 2: K2=(CR,-CR) K4=(0,-1) K6=(-CR,-CR)
        bfly4(er[2], ei[2], er[6], ei[6], er[10], ei[10], er[14], ei[14],
              (c1 + s1) * CR, (s1 - c1) * CR,
              s2,            -c2,
              (s3 - c3) * CR, -(c3 + s3) * CR);
        // k0 = 3: K3=(CB,-CA) K6=(-CR,-CR) K9=(-CA,CB)
        bfly4(er[3], ei[3], er[7], ei[7], er[11], ei[11], er[15], ei[15],
              c1 * CB + s1 * CA, s1 * CB - c1 * CA,
              (s2 - c2) * CR,   -(c2 + s2) * CR,
              -c3 * CA - s3 * CB, c3 * CB - s3 * CA);

        // stage d3 (L=256): tw uniform = W256^{q j}; W256^q = (W1024^q)^4 = (c2,s2)^2
        float vc1 = c2 * c2 - s2 * s2, vs1 = 2.0f * c2 * s2;
        float vc2 = vc1 * vc1 - vs1 * vs1, vs2 = 2.0f * vc1 * vs1;
        float vc3 = vc1 * vc2 - vs1 * vs2, vs3 = vc1 * vs2 + vs1 * vc2;
        #pragma unroll
        for (int b2 = 0; b2 < 4; ++b2)
            bfly4(er[4 * b2], ei[4 * b2], er[4 * b2 + 1], ei[4 * b2 + 1],
                  er[4 * b2 + 2], ei[4 * b2 + 2], er[4 * b2 + 3], ei[4 * b2 + 3],
                  vc1, vs1, vc2, vs2, vc3, vs3);
    }
    #pragma unroll
    for (int k = 0; k < 16; ++k)
        Z[PHYS(tid + 64 * k)] = make_float2(er[k], ei[k]);
    __syncthreads();

    // ================= Phase B: stages d2,d1 in regs =============================
    {
        const int H  = tid >> 2;
        const int d0 = tid & 3;
        float fr[16], fi[16];     // index d2*4 + d1
        #pragma unroll
        for (int d2 = 0; d2 < 4; ++d2)
            #pragma unroll
            for (int d1 = 0; d1 < 4; ++d1) {
                float2 v = Z[PHYS(64 * H + 16 * d2 + 4 * d1 + d0)];
                fr[4 * d2 + d1] = v.x; fi[4 * d2 + d1] = v.y;
            }

        float uc1, us1; __sincosf((float)d0 * (-6.283185307179586f / 64.0f), &us1, &uc1);

        // stage d2 (L=64): per d1, base b1 = W64^{d0} * W16^{d1}
        #pragma unroll
        for (int d1 = 0; d1 < 4; ++d1) {
            float bc1, bs1;
            if (d1 == 0)      { bc1 = uc1; bs1 = us1; }
            else if (d1 == 1) { bc1 = uc1 * CA + us1 * CB; bs1 = us1 * CA - uc1 * CB; }
            else if (d1 == 2) { bc1 = (uc1 + us1) * CR;    bs1 = (us1 - uc1) * CR; }
            else              { bc1 = uc1 * CB + us1 * CA; bs1 = us1 * CB - uc1 * CA; }
            float bc2 = bc1 * bc1 - bs1 * bs1, bs2 = 2.0f * bc1 * bs1;
            float bc3 = bc1 * bc2 - bs1 * bs2, bs3 = bc1 * bs2 + bs1 * bc2;
            bfly4(fr[d1], fi[d1], fr[4 + d1], fi[4 + d1],
                  fr[8 + d1], fi[8 + d1], fr[12 + d1], fi[12 + d1],
                  bc1, bs1, bc2, bs2, bc3, bs3);
        }

        // stage d1 (L=16): tw_j = (W16^{d0})^j, W16^{d0} = (W64^{d0})^4
        {
            float q2c = uc1 * uc1 - us1 * us1, q2s = 2.0f * uc1 * us1;
            float tc1 = q2c * q2c - q2s * q2s, ts1 = 2.0f * q2c * q2s;
            float tc2 = tc1 * tc1 - ts1 * ts1, ts2 = 2.0f * tc1 * ts1;
            float tc3 = tc1 * tc2 - ts1 * ts2, ts3 = tc1 * ts2 + ts1 * tc2;
            #pragma unroll
            for (int d2 = 0; d2 < 4; ++d2)
                bfly4(fr[4 * d2], fi[4 * d2], fr[4 * d2 + 1], fi[4 * d2 + 1],
                      fr[4 * d2 + 2], fi[4 * d2 + 2], fr[4 * d2 + 3], fi[4 * d2 + 3],
                      tc1, ts1, tc2, ts2, tc3, ts3);
        }

        __syncthreads();    // Z reads of Phase B done everywhere before rewrite

        // write back, skipping positions feeding dead final butterflies
        unsigned live16 = (p.live[H >> 1] >> ((H & 1) * 16)) & 0xFFFFu;
        #pragma unroll
        for (int d2 = 0; d2 < 4; ++d2)
            #pragma unroll
            for (int d1 = 0; d1 < 4; ++d1)
                if (live16 & (1u << (4 * d2 + d1)))
                    Z[PHYS(64 * H + 16 * d2 + 4 * d1 + d0)] =
                        make_float2(fr[4 * d2 + d1], fi[4 * d2 + d1]);
    }
    __syncthreads();

    // ================= Phase C: final stage d0, pruned to needed bins ============
    // butterfly B over positions {4B+c}: y0 -> bin r4(B); y3 -> bin 768+r4(B)
    #pragma unroll
    for (int it = 0; it < 2; ++it) {
        int k = tid + 64 * it;
        if (k < KU) {
            int B = R4(k);
            float2 a0 = Z[PHYS(4 * B)];
            float2 a1 = Z[PHYS(4 * B + 1)];
            float2 a2 = Z[PHYS(4 * B + 2)];
            float2 a3 = Z[PHYS(4 * B + 3)];
            SPA[k] = make_float2((a0.x + a2.x) + (a1.x + a3.x),
                                 (a0.y + a2.y) + (a1.y + a3.y));
        }
        int m = tid + 64 * it;
        if (m < 102) {
            int B = R4(154 + m);
            float2 a0 = Z[PHYS(4 * B)];
            float2 a1 = Z[PHYS(4 * B + 1)];
            float2 a2 = Z[PHYS(4 * B + 2)];
            float2 a3 = Z[PHYS(4 * B + 3)];
            float t2r = a0.x - a2.x, t2i = a0.y - a2.y;
            float t3r = a1.x - a3.x, t3i = a1.y - a3.y;
            SPB[m] = make_float2(t2r - t3i, t2i + t3r);
        }
    }
    __syncthreads();

    // ================= unpack rfft bins 0..102 (raw spectrum) ====================
    #pragma unroll
    for (int it = 0; it < 2; ++it) {
        int k = tid + 64 * it;
        if (k < KU) {
            float2 A  = SPA[k];
            float2 Bv = (k == 0) ? SPA[0] : SPB[102 - k];   // bin 1024-k
            float zer =  0.5f * (A.x + Bv.x);
            float zei =  0.5f * (A.y - Bv.y);
            float zor =  0.5f * (A.y + Bv.y);
            float zoi = -0.5f * (A.x - Bv.x);
            float sn, cs;
            __sincosf((float)k * (-3.141592653589793f / 1024.0f), &sn, &cs);
            SPX[k] = make_float2(zer + cs * zor - sn * zoi,
                                 zei + cs * zoi + sn * zor);
        }
    }
    __syncthreads();

    // ============ window as spectral conv: Xw = 0.5 X[k] - 0.25(X[k-1]+X[k+1]) ===
    #pragma unroll
    for (int it = 0; it < 2; ++it) {
        int k = tid + 64 * it;
        if (k < KLA) {
            float2 Xc = SPX[k];
            float2 Xp = SPX[k + 1];
            float2 Xm = (k == 0) ? make_float2(SPX[1].x, -SPX[1].y) : SPX[k - 1];
            float xr = 0.5f * Xc.x - 0.25f * (Xm.x + Xp.x);
            float xi = 0.5f * Xc.y - 0.25f * (Xm.y + Xp.y);
            LA[k] = __logf(sqrtf(xr * xr + xi * xi) + 1e-8f);
        }
    }
    __syncthreads();

    // ================= prefix sum of LA[0..101] by warp 0 ========================
    if (tid < 32) {
        float carry = 0.f;
        #pragma unroll
        for (int c = 0; c < 4; ++c) {
            int idx = c * 32 + tid;
            float v = (idx < KLA) ? LA[idx] : 0.f;
            #pragma unroll
            for (int o = 1; o < 32; o <<= 1) {
                float u = __shfl_up_sync(0xffffffffu, v, o);
                if (tid >= o) v += u;
            }
            float tot = __shfl_sync(0xffffffffu, v, 31);
            v += carry;
            if (idx < KLA) CS[idx + 1] = v;
            carry += tot;
        }
        if (tid == 0) CS[0] = 0.f;
    }
    __syncthreads();

    // ================= fine structure at the 256 pitch bins ======================
    #pragma unroll
    for (int u = 0; u < 4; ++u) {
        int pb = tid + 64 * u;
        int ci = p.closest[pb];          // 3..85
        int lo = ci - 15, hi = ci + 16;
        float sum = (lo < 0) ? ((float)(-lo) * LA[0] + CS[hi + 1])
                             : (CS[hi + 1] - CS[lo]);
        LS[pb] = __expf(LA[ci] - sum * (1.0f / (float)WINSZ));
    }
    __syncthreads();

    // ================= subharmonic summation + max + normalize ===================
    float v[4];
    float mloc = -3.4e38f;
    #pragma unroll
    for (int u = 0; u < 4; ++u) {
        int pb = tid + 64 * u;
        float acc = LS[pb];
        #pragma unroll
        for (int n = 1; n < 8; ++n) {
            int sh = p.shift[n];
            if (sh < NPITCH && pb >= sh) acc += p.wgt[n] * LS[pb - sh];
        }
        v[u] = acc;
        mloc = fmaxf(mloc, acc);
    }
    #pragma unroll
    for (int o = 16; o; o >>= 1)
        mloc = fmaxf(mloc, __shfl_xor_sync(0xffffffffu, mloc, o));
    if ((tid & 31) == 0) RED[tid >> 5] = mloc;
    __syncthreads();
    float mx = fmaxf(fmaxf(RED[0], RED[1]), 1e-8f);

    float* o0 = out + ((size_t)b * TFRAMES + t) * NPITCH;
    #pragma unroll
    for (int u = 0; u < 4; ++u)
        o0[tid + 64 * u] = __fdividef(v[u], mx);
}

extern "C" void kernel_launch(void* const* d_in, const int* in_sizes, int n_in,
                              void* d_out, int out_size)
{
    (void)in_sizes; (void)n_in; (void)out_size;
    const float* wav = (const float*)d_in[0];
    float* out = (float*)d_out;

    Params p;

    // Gather indices: f32 argmin over |linspace(0,12000,1025) - center_freq|
    const double l40 = log(40.0), l1000 = log(1000.0);
    for (int j = 0; j < NPITCH; ++j) {
        double cd = exp(l40 + (double)j * (l1000 - l40) / 255.0);
        float  cf = (float)cd;
        const float step = 11.71875f;
        int i0 = (int)(cd / 11.71875);
        int best = 0; float bestd = 3.4e38f;
        for (int i = i0 - 2; i <= i0 + 2; ++i) {
            int ic = i < 0 ? 0 : (i > 1024 ? 1024 : i);
            float d = fabsf((float)ic * step - cf);
            if (d < bestd) { bestd = d; best = ic; }
        }
        p.closest[j] = best;
    }

    // Harmonic shifts: Python round() == rint (half-even)
    const double cpb = 1200.0 * log2(25.0) / 255.0;
    p.shift[0] = 0; p.wgt[0] = 1.0f;
    for (int n = 2; n <= 8; ++n) {
        p.shift[n - 1] = (int)rint(1200.0 * log2((double)n) / cpb);
        p.wgt[n - 1]   = (float)pow(0.86, (double)(n - 1));
    }

    // liveness of final-stage butterflies: bin r4(B) <= 102 or >= 154 needed
    for (int wd = 0; wd < 8; ++wd) p.live[wd] = 0u;
    for (int B = 0; B < 256; ++B) {
        int rB = 64 * (B & 3) + 16 * ((B >> 2) & 3) + 4 * ((B >> 4) & 3) + ((B >> 6) & 3);
        if (rB <= 102 || rB >= 154)
            p.live[B >> 5] |= (1u << (B & 31));
    }

    dim3 grid(TFRAMES, BATCH);
    pitch_kernel<<<grid, 64>>>(wav, out, p);
}

// round 7
// speedup vs baseline: 7.0965x; 1.4603x over previous
#include <cuda_runtime.h>
#include <math.h>
#include <stdint.h>

// Fixed problem shapes
#define HOP 256
#define NFFT 2048
#define MH 1024
#define NPITCH 256
#define BATCH 16
#define NSAMP 480000
#define TFRAMES 1876
#define KU 103            // SPX bins 0..102
#define KLA 102           // LA bins 0..101
#define LPAD 168          // zero-pad in front of LS (max shift 165)

struct Params {
    int   closest[NPITCH];
    int   shift[8];
    float wgt[8];
};

// Phase A/B layout padding (conflict-free for strides 1 and 64)
__device__ __forceinline__ int PHYS(int i) { return i + 4 * (i >> 6); }
// Phase B-out / C-in: element c of final-butterfly-row r at 277*c + r + (r>>4).
// Injective: c-planes 277 apart; in-plane f(r)=r+(r>>4) strictly increasing, max 270.
__device__ __forceinline__ int QROW(int r) { return r + (r >> 4); }

__device__ __forceinline__ void bfly4(
    float& r0, float& i0, float& r1, float& i1,
    float& r2, float& i2, float& r3, float& i3,
    float c1, float s1, float c2, float s2, float c3, float s3)
{
    float t0r = r0 + r2, t0i = i0 + i2;
    float t1r = r1 + r3, t1i = i1 + i3;
    float t2r = r0 - r2, t2i = i0 - i2;
    float t3r = r1 - r3, t3i = i1 - i3;
    float y0r = t0r + t1r, y0i = t0i + t1i;
    float y2r = t0r - t1r, y2i = t0i - t1i;
    float y1r = t2r + t3i, y1i = t2i - t3r;
    float y3r = t2r - t3i, y3i = t2i + t3r;
    r0 = y0r;                 i0 = y0i;
    r1 = y1r * c1 - y1i * s1; i1 = y1r * s1 + y1i * c1;
    r2 = y2r * c2 - y2i * s2; i2 = y2r * s2 + y2i * c2;
    r3 = y3r * c3 - y3i * s3; i3 = y3r * s3 + y3i * c3;
}

#define CA 0.9238795325112867f
#define CB 0.3826834323650898f
#define CR 0.7071067811865476f

__global__ __launch_bounds__(64)
void pitch_kernel(const float* __restrict__ wav, float* __restrict__ out, Params p)
{
    __shared__ __align__(16) float2 Z[1104];          // A/B: PHYS (<=1083); B-out/C: planes (<=1101)
    __shared__ __align__(16) float2 SPX[KU];          // unpacked raw rfft bins 0..102
    __shared__ __align__(16) float  LA[104];          // log mag (102,103 zero)
    __shared__ __align__(16) float  CS1[104];         // inclusive prefix sums of LA
    __shared__ __align__(16) float  LSB[LPAD + NPITCH];
    __shared__ float RED[2];

    const int tid = threadIdx.x;     // 0..63
    const int t   = blockIdx.x;
    const int b   = blockIdx.y;
    const float* w = wav + (size_t)b * NSAMP;
    const int base = t * HOP - (NFFT / 2);

    // zero LS front padding (consumed much later, after several barriers)
    if (tid < LPAD / 4)
        reinterpret_cast<float4*>(LSB)[tid] = make_float4(0.f, 0.f, 0.f, 0.f);

    // ================= Phase A: load + stages d4,d3 in regs ======================
    float er[16], ei[16];
    if (base >= 0 && base + NFFT <= NSAMP) {
        const float2* src = reinterpret_cast<const float2*>(w + base);
        #pragma unroll
        for (int k = 0; k < 16; ++k) {
            float2 xv = src[tid + 64 * k];
            er[k] = xv.x; ei[k] = xv.y;
        }
    } else {
        #pragma unroll
        for (int k = 0; k < 16; ++k) {
            int n  = tid + 64 * k;
            int p0 = base + 2 * n, p1 = p0 + 1;
            p0 = p0 < 0 ? -p0 : (p0 >= NSAMP ? 2 * NSAMP - 2 - p0 : p0);
            p1 = p1 < 0 ? -p1 : (p1 >= NSAMP ? 2 * NSAMP - 2 - p1 : p1);
            er[k] = w[p0]; ei[k] = w[p1];
        }
    }

    {
        float c1, s1; __sincosf((float)tid * (-6.283185307179586f / 1024.0f), &s1, &c1);
        float c2 = c1 * c1 - s1 * s1, s2 = 2.0f * c1 * s1;
        float c3 = c1 * c2 - s1 * s2, s3 = c1 * s2 + s1 * c2;
        bfly4(er[0], ei[0], er[4], ei[4], er[8], ei[8], er[12], ei[12],
              c1, s1, c2, s2, c3, s3);
        bfly4(er[1], ei[1], er[5], ei[5], er[9], ei[9], er[13], ei[13],
              c1 * CA + s1 * CB, s1 * CA - c1 * CB,
              (c2 + s2) * CR,    (s2 - c2) * CR,
              c3 * CB + s3 * CA, s3 * CB - c3 * CA);
        bfly4(er[2], ei[2], er[6], ei[6], er[10], ei[10], er[14], ei[14],
              (c1 + s1) * CR, (s1 - c1) * CR,
              s2,            -c2,
              (s3 - c3) * CR, -(c3 + s3) * CR);
        bfly4(er[3], ei[3], er[7], ei[7], er[11], ei[11], er[15], ei[15],
              c1 * CB + s1 * CA, s1 * CB - c1 * CA,
              (s2 - c2) * CR,   -(c2 + s2) * CR,
              -c3 * CA - s3 * CB, c3 * CB - s3 * CA);

        float vc1 = c2 * c2 - s2 * s2, vs1 = 2.0f * c2 * s2;
        float vc2 = vc1 * vc1 - vs1 * vs1, vs2 = 2.0f * vc1 * vs1;
        float vc3 = vc1 * vc2 - vs1 * vs2, vs3 = vc1 * vs2 + vs1 * vc2;
        #pragma unroll
        for (int b2 = 0; b2 < 4; ++b2)
            bfly4(er[4 * b2], ei[4 * b2], er[4 * b2 + 1], ei[4 * b2 + 1],
                  er[4 * b2 + 2], ei[4 * b2 + 2], er[4 * b2 + 3], ei[4 * b2 + 3],
                  vc1, vs1, vc2, vs2, vc3, vs3);
    }
    #pragma unroll
    for (int k = 0; k < 16; ++k)
        Z[PHYS(tid + 64 * k)] = make_float2(er[k], ei[k]);
    __syncthreads();

    // ================= Phase B: stages d2,d1 in regs =============================
    {
        const int H  = tid >> 2;
        const int d0 = tid & 3;
        const int h  = 4 * (H & 3) + (H >> 2);
        float fr[16], fi[16];     // index 4*d2 + d1
        #pragma unroll
        for (int d2 = 0; d2 < 4; ++d2)
            #pragma unroll
            for (int d1 = 0; d1 < 4; ++d1) {
                float2 v = Z[PHYS(64 * H + 16 * d2 + 4 * d1 + d0)];
                fr[4 * d2 + d1] = v.x; fi[4 * d2 + d1] = v.y;
            }

        float uc1, us1; __sincosf((float)d0 * (-6.283185307179586f / 64.0f), &us1, &uc1);

        #pragma unroll
        for (int d1 = 0; d1 < 4; ++d1) {
            float bc1, bs1;
            if (d1 == 0)      { bc1 = uc1; bs1 = us1; }
            else if (d1 == 1) { bc1 = uc1 * CA + us1 * CB; bs1 = us1 * CA - uc1 * CB; }
            else if (d1 == 2) { bc1 = (uc1 + us1) * CR;    bs1 = (us1 - uc1) * CR; }
            else              { bc1 = uc1 * CB + us1 * CA; bs1 = us1 * CB - uc1 * CA; }
            float bc2 = bc1 * bc1 - bs1 * bs1, bs2 = 2.0f * bc1 * bs1;
            float bc3 = bc1 * bc2 - bs1 * bs2, bs3 = bc1 * bs2 + bs1 * bc2;
            bfly4(fr[d1], fi[d1], fr[4 + d1], fi[4 + d1],
                  fr[8 + d1], fi[8 + d1], fr[12 + d1], fi[12 + d1],
                  bc1, bs1, bc2, bs2, bc3, bs3);
        }
        {
            float q2c = uc1 * uc1 - us1 * us1, q2s = 2.0f * uc1 * us1;
            float tc1 = q2c * q2c - q2s * q2s, ts1 = 2.0f * q2c * q2s;
            float tc2 = tc1 * tc1 - ts1 * ts1, ts2 = 2.0f * tc1 * ts1;
            float tc3 = tc1 * tc2 - ts1 * ts2, ts3 = tc1 * ts2 + ts1 * tc2;
            #pragma unroll
            for (int d2 = 0; d2 < 4; ++d2)
                bfly4(fr[4 * d2], fi[4 * d2], fr[4 * d2 + 1], fi[4 * d2 + 1],
                      fr[4 * d2 + 2], fi[4 * d2 + 2], fr[4 * d2 + 3], fi[4 * d2 + 3],
                      tc1, ts1, tc2, ts2, tc3, ts3);
        }

        __syncthreads();    // all PHYS reads complete before relayout rewrite

        // writeback bin-indexed: final bin row of butterfly B=16H+4d2+d1 is
        // r = 16W + h with W = 4*d1 + d2. Element c=d0 at 277*d0 + 17W + h.
        // Liveness (r<=102 or r>=154): W 7,8 dead; W6 needs h<=6; W9 needs h>=10.
        #pragma unroll
        for (int d2 = 0; d2 < 4; ++d2)
            #pragma unroll
            for (int d1 = 0; d1 < 4; ++d1) {
                const int W = 4 * d1 + d2;
                if (W == 7 || W == 8) continue;
                bool store = true;
                if (W == 6) store = (h <= 6);
                if (W == 9) store = (h >= 10);
                if (store)
                    Z[277 * d0 + 17 * W + h] =
                        make_float2(fr[4 * d2 + d1], fi[4 * d2 + d1]);
            }
    }
    __syncthreads();

    // ========== Phase C (fused): final stage + rfft unpack -> SPX[0..102] ========
    #pragma unroll
    for (int it = 0; it < 2; ++it) {
        int k = tid + 64 * it;
        if (k < KU) {
            int ra = QROW(k);
            float2 a0 = Z[ra];
            float2 a1 = Z[ra + 277];
            float2 a2 = Z[ra + 554];
            float2 a3 = Z[ra + 831];
            float Ar = (a0.x + a2.x) + (a1.x + a3.x);
            float Ai = (a0.y + a2.y) + (a1.y + a3.y);
            float Br, Bi;
            if (k == 0) { Br = Ar; Bi = Ai; }
            else {
                int rb = QROW(256 - k);
                float2 b0 = Z[rb];
                float2 b1 = Z[rb + 277];
                float2 b2 = Z[rb + 554];
                float2 b3 = Z[rb + 831];
                float t2r = b0.x - b2.x, t2i = b0.y - b2.y;
                float t3r = b1.x - b3.x, t3i = b1.y - b3.y;
                Br = t2r - t3i; Bi = t2i + t3r;       // y3 -> bin 1024-k
            }
            float zer =  0.5f * (Ar + Br);
            float zei =  0.5f * (Ai - Bi);
            float zor =  0.5f * (Ai + Bi);
            float zoi = -0.5f * (Ar - Br);
            float sn, cs;
            __sincosf((float)k * (-3.141592653589793f / 1024.0f), &sn, &cs);
            SPX[k] = make_float2(zer + cs * zor - sn * zoi,
                                 zei + cs * zoi + sn * zor);
        }
    }
    __syncthreads();

    // ====== window as spectral conv: Xw = 0.5 X[k] - 0.25(X[k-1]+X[k+1]) ========
    #pragma unroll
    for (int it = 0; it < 2; ++it) {
        int k = tid + 64 * it;
        if (k < KLA) {
            float2 Xc = SPX[k];
            float2 Xp = SPX[k + 1];
            float2 Xm = (k == 0) ? make_float2(SPX[1].x, -SPX[1].y) : SPX[k - 1];
            float xr = 0.5f * Xc.x - 0.25f * (Xm.x + Xp.x);
            float xi = 0.5f * Xc.y - 0.25f * (Xm.y + Xp.y);
            LA[k] = __logf(sqrtf(xr * xr + xi * xi) + 1e-8f);
        }
    }
    if (tid < 2) LA[KLA + tid] = 0.f;
    __syncthreads();

    // ================= single-pass scan (warp 0): CS1 inclusive ==================
    if (tid < 32) {
        float v0 = 0.f, v1 = 0.f, v2 = 0.f, v3 = 0.f;
        if (tid < 26) {
            float4 q = reinterpret_cast<const float4*>(LA)[tid];
            v0 = q.x; v1 = q.y; v2 = q.z; v3 = q.w;
        }
        float p1 = v0 + v1, p2 = p1 + v2, p3 = p2 + v3;
        float s = p3;
        #pragma unroll
        for (int o = 1; o < 32; o <<= 1) {
            float u = __shfl_up_sync(0xffffffffu, s, o);
            if (tid >= o) s += u;
        }
        float excl = s - p3;
        if (tid < 26)
            reinterpret_cast<float4*>(CS1)[tid] =
                make_float4(excl + v0, excl + p1, excl + p2, excl + p3);
    }
    __syncthreads();

    // ============ fine structure: 4 consecutive pitch bins per thread ============
    float lsv[4];
    {
        int4 c4 = reinterpret_cast<const int4*>(p.closest)[tid];
        int cis[4] = {c4.x, c4.y, c4.z, c4.w};
        float LA0 = LA[0];
        #pragma unroll
        for (int j = 0; j < 4; ++j) {
            int ci = cis[j];                  // 3..85
            int lo = ci - 15, hi = ci + 16;   // hi <= 101
            float sum = (lo <= 0) ? fmaf((float)(-lo), LA0, CS1[hi])
                                  : CS1[hi] - CS1[lo - 1];
            lsv[j] = __expf(LA[ci] - sum * 0.03125f);
        }
        *reinterpret_cast<float4*>(&LSB[LPAD + 4 * tid]) =
            make_float4(lsv[0], lsv[1], lsv[2], lsv[3]);
    }
    __syncthreads();

    // ================= subharmonic summation (zero-padded, guard-free) ==========
    float acc[4] = {lsv[0], lsv[1], lsv[2], lsv[3]};
    #pragma unroll
    for (int n = 1; n < 8; ++n) {
        int   sh = p.shift[n];
        float wn = p.wgt[n];
        int   bi = LPAD + 4 * tid - sh;       // >= 3 always
        if ((sh & 3) == 0) {
            float4 q = *reinterpret_cast<const float4*>(&LSB[bi]);
            acc[0] = fmaf(wn, q.x, acc[0]);
            acc[1] = fmaf(wn, q.y, acc[1]);
            acc[2] = fmaf(wn, q.z, acc[2]);
            acc[3] = fmaf(wn, q.w, acc[3]);
        } else if ((sh & 1) == 0) {
            float2 qa = *reinterpret_cast<const float2*>(&LSB[bi]);
            float2 qb = *reinterpret_cast<const float2*>(&LSB[bi + 2]);
            acc[0] = fmaf(wn, qa.x, acc[0]);
            acc[1] = fmaf(wn, qa.y, acc[1]);
            acc[2] = fmaf(wn, qb.x, acc[2]);
            acc[3] = fmaf(wn, qb.y, acc[3]);
        } else {
            #pragma unroll
            for (int j = 0; j < 4; ++j)
                acc[j] = fmaf(wn, LSB[bi + j], acc[j]);
        }
    }

    // ================= per-frame max, normalize, store ===========================
    float mloc = fmaxf(fmaxf(acc[0], acc[1]), fmaxf(acc[2], acc[3]));
    #pragma unroll
    for (int o = 16; o; o >>= 1)
        mloc = fmaxf(mloc, __shfl_xor_sync(0xffffffffu, mloc, o));
    if ((tid & 31) == 0) RED[tid >> 5] = mloc;
    __syncthreads();
    float mx = fmaxf(fmaxf(RED[0], RED[1]), 1e-8f);

    float4 o4;
    o4.x = __fdividef(acc[0], mx);
    o4.y = __fdividef(acc[1], mx);
    o4.z = __fdividef(acc[2], mx);
    o4.w = __fdividef(acc[3], mx);
    reinterpret_cast<float4*>(out + ((size_t)b * TFRAMES + t) * NPITCH)[tid] = o4;
}

extern "C" void kernel_launch(void* const* d_in, const int* in_sizes, int n_in,
                              void* d_out, int out_size)
{
    (void)in_sizes; (void)n_in; (void)out_size;
    const float* wav = (const float*)d_in[0];
    float* out = (float*)d_out;

    Params p;

    // Gather indices: f32 argmin over |linspace(0,12000,1025) - center_freq|
    const double l40 = log(40.0), l1000 = log(1000.0);
    for (int j = 0; j < NPITCH; ++j) {
        double cd = exp(l40 + (double)j * (l1000 - l40) / 255.0);
        float  cf = (float)cd;
        const float step = 11.71875f;
        int i0 = (int)(cd / 11.71875);
        int best = 0; float bestd = 3.4e38f;
        for (int i = i0 - 2; i <= i0 + 2; ++i) {
            int ic = i < 0 ? 0 : (i > 1024 ? 1024 : i);
            float d = fabsf((float)ic * step - cf);
            if (d < bestd) { bestd = d; best = ic; }
        }
        p.closest[j] = best;
    }

    // Harmonic shifts: Python round() == rint (half-even), identical expression
    const double cpb = 1200.0 * log2(25.0) / 255.0;
    p.shift[0] = 0; p.wgt[0] = 1.0f;
    for (int n = 2; n <= 8; ++n) {
        p.shift[n - 1] = (int)rint(1200.0 * log2((double)n) / cpb);
        p.wgt[n - 1]   = (float)pow(0.86, (double)(n - 1));
    }

    dim3 grid(TFRAMES, BATCH);
    pitch_kernel<<<grid, 64>>>(wav, out, p);
}